// round 1
// baseline (speedup 1.0000x reference)
#include <cuda_runtime.h>
#include <math.h>

#ifndef M_PI
#define M_PI 3.14159265358979323846
#endif

#define NB     80
#define NFFT   512
#define HOPL   128
#define PADS   256
#define NFREQ  257
#define NFRM   2000
#define BATCH  32
#define LEN    320000
#define TFR    2501                 // LEN/HOPL + 1
#define LPAD   (LEN + 2*PADS)      // 320512

// ---- static device scratch (allocation-free rule) ----
__device__ float d_win[NFFT];
__device__ float d_win2[NFFT];
__device__ float d_twr[NFFT/2];
__device__ float d_twi[NFFT/2];
__device__ int   d_band[NFREQ];
__device__ float d_ola[BATCH * LPAD];          // ~41 MB
__device__ unsigned int d_maxb[BATCH];

// ---------------------------------------------------------------------------
// Init: window, window^2, twiddles, mel band table (double precision to match
// the numpy reference edge behavior, including the Nyquist bin falling outside
// the last band).
// ---------------------------------------------------------------------------
__global__ void init_tables_k() {
    __shared__ float s_edges[NB + 1];
    int j = threadIdx.x;

    if (j <= NB) {
        double mel_max = 2595.0 * log10(1.0 + 8000.0 / 700.0);
        double delta   = mel_max / (double)NB;
        double mel     = (j == NB) ? mel_max : (double)j * delta;  // numpy linspace endpoint exact
        double hz      = 700.0 * (pow(10.0, mel / 2595.0) - 1.0);
        s_edges[j]     = (float)(hz / 8000.0);
    }
    if (j < NFFT) {
        double w = 0.5 * (1.0 - cos(2.0 * M_PI * (double)j / (double)NFFT));
        d_win[j]  = (float)w;
        d_win2[j] = (float)(w * w);
    }
    if (j < NFFT/2) {
        double ang = -2.0 * M_PI * (double)j / (double)NFFT;
        d_twr[j] = (float)cos(ang);
        d_twi[j] = (float)sin(ang);
    }
    __syncthreads();
    if (j < NFREQ) {
        float freq = (float)j / 256.0f;                  // exact (power of 2)
        int idx = 0;
        #pragma unroll 1
        for (int e = 0; e <= NB; ++e) idx += (s_edges[e] <= freq) ? 1 : 0;  // searchsorted 'right'
        int band = idx - 1;
        d_band[j] = (band >= 0 && band < NB) ? band : -1;
    }
}

// ---------------------------------------------------------------------------
__global__ void zero_k() {
    int i = blockIdx.x * blockDim.x + threadIdx.x;
    int n = BATCH * LPAD;
    for (int p = i; p < n; p += gridDim.x * blockDim.x) d_ola[p] = 0.0f;
    if (i < BATCH) d_maxb[i] = 0u;
}

// ---------------------------------------------------------------------------
// One block per (frame t, batch b). 128 threads.
// Forward DIF (natural -> bitrev), mask multiply in bitrev order,
// inverse DIT (bitrev -> natural). atomicAdd overlap-add into d_ola.
// ---------------------------------------------------------------------------
__global__ __launch_bounds__(128) void frame_k(const float* __restrict__ mag,
                                               const float* __restrict__ noise) {
    const int t   = blockIdx.x;
    const int b   = blockIdx.y;
    const int tid = threadIdx.x;

    __shared__ float re[NFFT], im[NFFT];
    __shared__ float s_twr[NFFT/2], s_twi[NFFT/2];
    __shared__ float s_win[NFFT];
    __shared__ float s_mask[NFREQ];
    __shared__ float s_m[NB];

    // phase 1: tables + interpolated band magnitudes
    #pragma unroll
    for (int r = 0; r < 2; ++r) {
        int k = tid + r * 128;
        s_twr[k] = d_twr[k];
        s_twi[k] = d_twi[k];
    }
    #pragma unroll
    for (int r = 0; r < 4; ++r) {
        int k = tid + r * 128;
        s_win[k] = d_win[k];
    }
    if (tid < NB) {
        double pos = (double)t * (1999.0 / 2500.0);
        int   i0  = (int)pos;
        float wfr = (float)(pos - (double)i0);
        int   i1  = min(i0 + 1, NFRM - 1);
        const float* mrow = mag + ((size_t)b * NB + tid) * NFRM;
        s_m[tid] = mrow[i0] * (1.0f - wfr) + mrow[i1] * wfr;
    }
    __syncthreads();

    // phase 2: mask expansion + windowed frame load (reflect padding)
    for (int f = tid; f < NFREQ; f += 128) {
        int bd = d_band[f];
        s_mask[f] = (bd >= 0) ? s_m[bd] : 0.0f;
    }
    {
        const float* nb_ = noise + (size_t)b * LEN;
        int base = t * HOPL - PADS;
        #pragma unroll
        for (int r = 0; r < 4; ++r) {
            int jj = tid + r * 128;
            int m  = base + jj;
            if (m < 0)         m = -m;
            else if (m >= LEN) m = 2 * LEN - 2 - m;
            re[jj] = nb_[m] * s_win[jj];
            im[jj] = 0.0f;
        }
    }

    // ---- forward FFT: DIF radix-2, natural in -> bit-reversed out ----
    #pragma unroll
    for (int ls = 8; ls >= 0; --ls) {
        const int s = 1 << ls;
        __syncthreads();
        #pragma unroll
        for (int r = 0; r < 2; ++r) {
            int q = tid + r * 128;
            int j = q & (s - 1);
            int i = ((q >> ls) << (ls + 1)) | j;
            float ar = re[i],     ai = im[i];
            float br = re[i + s], bi = im[i + s];
            re[i] = ar + br;  im[i] = ai + bi;
            float dr = ar - br, di = ai - bi;
            int   k  = j << (8 - ls);
            float wr = s_twr[k], wi = s_twi[k];
            re[i + s] = dr * wr - di * wi;
            im[i + s] = dr * wi + di * wr;
        }
    }
    __syncthreads();

    // ---- pointwise mask multiply (data is bit-reversed: freq = brev9(p)) ----
    #pragma unroll
    for (int r = 0; r < 4; ++r) {
        int p = tid + r * 128;
        int f = __brev((unsigned)p) >> 23;       // 9-bit reversal
        f = (f <= 256) ? f : 512 - f;
        float mm = s_mask[f];
        re[p] *= mm;
        im[p] *= mm;
    }

    // ---- inverse FFT: DIT radix-2, bit-reversed in -> natural out ----
    #pragma unroll
    for (int ls = 0; ls <= 8; ++ls) {
        const int s = 1 << ls;
        __syncthreads();
        #pragma unroll
        for (int r = 0; r < 2; ++r) {
            int q = tid + r * 128;
            int j = q & (s - 1);
            int i = ((q >> ls) << (ls + 1)) | j;
            int   k  = j << (8 - ls);
            float wr = s_twr[k], wi = -s_twi[k];  // conjugate twiddle
            float br = re[i + s], bi = im[i + s];
            float vr = br * wr - bi * wi;
            float vi = br * wi + bi * wr;
            float ar = re[i], ai = im[i];
            re[i]     = ar + vr;  im[i]     = ai + vi;
            re[i + s] = ar - vr;  im[i + s] = ai - vi;
        }
    }
    __syncthreads();

    // ---- windowed overlap-add ----
    {
        float* olab = d_ola + (size_t)b * LPAD + (size_t)t * HOPL;
        const float scale = 1.0f / (float)NFFT;
        #pragma unroll
        for (int r = 0; r < 4; ++r) {
            int jj = tid + r * 128;
            atomicAdd(&olab[jj], re[jj] * s_win[jj] * scale);
        }
    }
}

// ---------------------------------------------------------------------------
// Exact window-square OLA denominator at padded index p (<=4 frames overlap).
// ---------------------------------------------------------------------------
__device__ __forceinline__ float denom_at(int p) {
    int k0 = p & (HOPL - 1);
    int tb = p >> 7;
    float s = 0.0f;
    #pragma unroll
    for (int jj = 0; jj < 4; ++jj) {
        int tt = tb - jj;
        if (tt >= 0 && tt <= TFR - 1) s += d_win2[k0 + (jj << 7)];
    }
    return (s > 1e-11f) ? s : 1.0f;
}

// ---------------------------------------------------------------------------
__global__ void max_k() {
    const int b   = blockIdx.y;
    const int tid = threadIdx.x;
    __shared__ float s_red[256];
    float m = 0.0f;
    for (int n = blockIdx.x * 256 + tid; n < LEN; n += gridDim.x * 256) {
        int p = n + PADS;
        float y = d_ola[(size_t)b * LPAD + p] / denom_at(p);
        m = fmaxf(m, fabsf(y));
    }
    s_red[tid] = m;
    __syncthreads();
    for (int off = 128; off > 0; off >>= 1) {
        if (tid < off) s_red[tid] = fmaxf(s_red[tid], s_red[tid + off]);
        __syncthreads();
    }
    if (tid == 0) atomicMax(&d_maxb[b], __float_as_uint(s_red[0]));
}

__global__ void norm_k(float* __restrict__ out) {
    const int b = blockIdx.y;
    const int n = blockIdx.x * 256 + threadIdx.x;
    if (n >= LEN) return;
    float mx  = __uint_as_float(d_maxb[b]);
    float inv = 1.0f / (mx + 1e-8f);
    int p = n + PADS;
    float y = d_ola[(size_t)b * LPAD + p] / denom_at(p);
    out[(size_t)b * LEN + n] = y * inv;
}

// ---------------------------------------------------------------------------
extern "C" void kernel_launch(void* const* d_in, const int* in_sizes, int n_in,
                              void* d_out, int out_size) {
    (void)in_sizes; (void)n_in; (void)out_size;
    const float* mag   = (const float*)d_in[0];   // [32, 80, 2000]
    const float* noise = (const float*)d_in[1];   // [32, 320000]
    float* out = (float*)d_out;                   // [32, 320000]

    init_tables_k<<<1, 512>>>();
    zero_k<<<8192, 256>>>();
    frame_k<<<dim3(TFR, BATCH), 128>>>(mag, noise);
    max_k<<<dim3(128, BATCH), 256>>>();
    norm_k<<<dim3((LEN + 255) / 256, BATCH), 256>>>(out);
}

// round 2
// speedup vs baseline: 1.6324x; 1.6324x over previous
#include <cuda_runtime.h>
#include <math.h>

#ifndef M_PI
#define M_PI 3.14159265358979323846
#endif

#define NB     80
#define NFFT   512
#define HOPL   128
#define PADS   256
#define NFREQ  257
#define NFRM   2000
#define BATCH  32
#define LEN    320000
#define TFR    2501                 // LEN/HOPL + 1
#define TPAD   2502                 // padded frame count (even)
#define NPAIR  1251

// ---- static device scratch (allocation-free rule) ----
__device__ float d_win[NFFT];
__device__ float d_win2[NFFT];
__device__ float d_twr[NFFT/2];
__device__ float d_twi[NFFT/2];
__device__ int   d_band[NFREQ];
__device__ float d_yf[(size_t)BATCH * TPAD * NFFT];   // ~164 MB frame outputs
__device__ float d_y[(size_t)BATCH * LEN];            // ~41 MB un-normalized audio
__device__ unsigned int d_maxb[BATCH];

__device__ __forceinline__ int brev9(int p) {
    return (int)(__brev((unsigned)p) >> 23);
}

// ---------------------------------------------------------------------------
// Init: window, window^2, twiddles, mel band table (double precision to match
// numpy reference edges incl. Nyquist bin outside last band). Also zero maxes.
// ---------------------------------------------------------------------------
__global__ void init_tables_k() {
    __shared__ float s_edges[NB + 1];
    int j = threadIdx.x;

    if (j <= NB) {
        double mel_max = 2595.0 * log10(1.0 + 8000.0 / 700.0);
        double delta   = mel_max / (double)NB;
        double mel     = (j == NB) ? mel_max : (double)j * delta;
        double hz      = 700.0 * (pow(10.0, mel / 2595.0) - 1.0);
        s_edges[j]     = (float)(hz / 8000.0);
    }
    if (j < NFFT) {
        double w = 0.5 * (1.0 - cos(2.0 * M_PI * (double)j / (double)NFFT));
        d_win[j]  = (float)w;
        d_win2[j] = (float)(w * w);
    }
    if (j < NFFT/2) {
        double ang = -2.0 * M_PI * (double)j / (double)NFFT;
        d_twr[j] = (float)cos(ang);
        d_twi[j] = (float)sin(ang);
    }
    if (j < BATCH) d_maxb[j] = 0u;
    __syncthreads();
    if (j < NFREQ) {
        float freq = (float)j / 256.0f;
        int idx = 0;
        #pragma unroll 1
        for (int e = 0; e <= NB; ++e) idx += (s_edges[e] <= freq) ? 1 : 0;  // searchsorted 'right'
        int band = idx - 1;
        d_band[j] = (band >= 0 && band < NB) ? band : -1;
    }
}

// ---------------------------------------------------------------------------
// One block per (frame-pair q, batch b). 128 threads.
// z = win*x(2q) + i*win*x(2q+1); forward DIF FFT (natural -> bitrev);
// combined two-frame mask  W = a*Z + d*conj(Z[N-k])  applied in bitrev layout;
// inverse DIT FFT (bitrev -> natural); y0=Re, y1=Im written coalesced.
// ---------------------------------------------------------------------------
__global__ __launch_bounds__(128) void frame_k(const float* __restrict__ mag,
                                               const float* __restrict__ noise) {
    const int q   = blockIdx.x;
    const int b   = blockIdx.y;
    const int tid = threadIdx.x;
    const int t0  = 2 * q;
    const int t1  = 2 * q + 1;
    const bool t1v = (t1 < TFR);
    const int t1c = t1v ? t1 : (TFR - 1);

    __shared__ float re[NFFT], im[NFFT];
    __shared__ float s_twr[NFFT/2], s_twi[NFFT/2];
    __shared__ float s_win[NFFT];
    __shared__ float s_a[NFREQ], s_d[NFREQ];
    __shared__ float s_m0[NB], s_m1[NB];

    // phase 1: tables + interpolated band magnitudes for both frames
    #pragma unroll
    for (int r = 0; r < 2; ++r) {
        int k = tid + r * 128;
        s_twr[k] = d_twr[k];
        s_twi[k] = d_twi[k];
    }
    #pragma unroll
    for (int r = 0; r < 4; ++r) {
        int k = tid + r * 128;
        s_win[k] = d_win[k];
    }
    if (tid < NB) {
        const float* mrow = mag + ((size_t)b * NB + tid) * NFRM;
        {
            double pos = (double)t0 * (1999.0 / 2500.0);
            int   i0  = (int)pos;
            float wfr = (float)(pos - (double)i0);
            int   i1  = min(i0 + 1, NFRM - 1);
            s_m0[tid] = mrow[i0] * (1.0f - wfr) + mrow[i1] * wfr;
        }
        {
            double pos = (double)t1c * (1999.0 / 2500.0);
            int   i0  = (int)pos;
            float wfr = (float)(pos - (double)i0);
            int   i1  = min(i0 + 1, NFRM - 1);
            s_m1[tid] = mrow[i0] * (1.0f - wfr) + mrow[i1] * wfr;
        }
    }
    __syncthreads();

    // phase 2: combined mask coefficients + packed windowed frame load
    for (int f = tid; f < NFREQ; f += 128) {
        int bd = d_band[f];
        float m0 = (bd >= 0) ? s_m0[bd] : 0.0f;
        float m1 = (bd >= 0) ? s_m1[bd] : 0.0f;
        s_a[f] = 0.5f * (m0 + m1);
        s_d[f] = 0.5f * (m0 - m1);
    }
    {
        const float* nb_ = noise + (size_t)b * LEN;
        int base = t0 * HOPL - PADS;
        #pragma unroll
        for (int r = 0; r < 4; ++r) {
            int jj = tid + r * 128;
            int m0i = base + jj;
            if (m0i < 0)         m0i = -m0i;
            else if (m0i >= LEN) m0i = 2 * LEN - 2 - m0i;
            int m1i = base + HOPL + jj;
            if (m1i < 0)         m1i = -m1i;
            else if (m1i >= LEN) m1i = 2 * LEN - 2 - m1i;
            float w = s_win[jj];
            re[jj] = nb_[m0i] * w;
            im[jj] = nb_[m1i] * w;
        }
    }

    // ---- forward FFT: DIF radix-2, natural in -> bit-reversed out ----
    #pragma unroll
    for (int ls = 8; ls >= 0; --ls) {
        const int s = 1 << ls;
        __syncthreads();
        #pragma unroll
        for (int r = 0; r < 2; ++r) {
            int qq = tid + r * 128;
            int j = qq & (s - 1);
            int i = ((qq >> ls) << (ls + 1)) | j;
            float ar = re[i],     ai = im[i];
            float br = re[i + s], bi = im[i + s];
            re[i] = ar + br;  im[i] = ai + bi;
            float dr = ar - br, di = ai - bi;
            int   k  = j << (8 - ls);
            float wr = s_twr[k], wi = s_twi[k];
            re[i + s] = dr * wr - di * wi;
            im[i + s] = dr * wi + di * wr;
        }
    }
    __syncthreads();

    // ---- two-frame mask in bitrev layout: W[k] = a*Z[k] + d*conj(Z[N-k]) ----
    {
        float nr[4], ni[4];
        #pragma unroll
        for (int r = 0; r < 4; ++r) {
            int p  = tid + r * 128;
            int k  = brev9(p);
            int p2 = brev9((NFFT - k) & (NFFT - 1));
            int f  = (k <= 256) ? k : NFFT - k;
            float a  = s_a[f];
            float dd = s_d[f];
            float zr = re[p],  zi = im[p];
            float cr = re[p2], ci = im[p2];
            nr[r] = a * zr + dd * cr;
            ni[r] = a * zi - dd * ci;
        }
        __syncthreads();
        #pragma unroll
        for (int r = 0; r < 4; ++r) {
            int p = tid + r * 128;
            re[p] = nr[r];
            im[p] = ni[r];
        }
    }

    // ---- inverse FFT: DIT radix-2, bit-reversed in -> natural out ----
    #pragma unroll
    for (int ls = 0; ls <= 8; ++ls) {
        const int s = 1 << ls;
        __syncthreads();
        #pragma unroll
        for (int r = 0; r < 2; ++r) {
            int qq = tid + r * 128;
            int j = qq & (s - 1);
            int i = ((qq >> ls) << (ls + 1)) | j;
            int   k  = j << (8 - ls);
            float wr = s_twr[k], wi = -s_twi[k];  // conjugate twiddle
            float br = re[i + s], bi = im[i + s];
            float vr = br * wr - bi * wi;
            float vi = br * wi + bi * wr;
            float ar = re[i], ai = im[i];
            re[i]     = ar + vr;  im[i]     = ai + vi;
            re[i + s] = ar - vr;  im[i + s] = ai - vi;
        }
    }
    __syncthreads();

    // ---- windowed frame outputs, coalesced (y0 = Re, y1 = Im) ----
    {
        const float scale = 1.0f / (float)NFFT;
        float* y0 = d_yf + ((size_t)b * TPAD + t0) * NFFT;
        #pragma unroll
        for (int r = 0; r < 4; ++r) {
            int jj = tid + r * 128;
            y0[jj] = re[jj] * (s_win[jj] * scale);
        }
        if (t1v) {
            float* y1 = d_yf + ((size_t)b * TPAD + t1) * NFFT;
            #pragma unroll
            for (int r = 0; r < 4; ++r) {
                int jj = tid + r * 128;
                y1[jj] = im[jj] * (s_win[jj] * scale);
            }
        }
    }
}

// ---------------------------------------------------------------------------
// Exact window-square OLA denominator at padded index p (<=4 frames overlap).
// ---------------------------------------------------------------------------
__device__ __forceinline__ float denom_at(int p) {
    int k0 = p & (HOPL - 1);
    int tb = p >> 7;
    float s = 0.0f;
    #pragma unroll
    for (int jj = 0; jj < 4; ++jj) {
        int tt = tb - jj;
        if (tt >= 0 && tt <= TFR - 1) s += d_win2[k0 + (jj << 7)];
    }
    return (s > 1e-11f) ? s : 1.0f;
}

// ---------------------------------------------------------------------------
// Gather overlap-add (<=4 frames per sample), normalize by window-square,
// write un-normalized y, fused per-batch max reduction.
// ---------------------------------------------------------------------------
__global__ __launch_bounds__(256) void gather_k() {
    const int b   = blockIdx.y;
    const int tid = threadIdx.x;
    __shared__ float s_red[256];
    float m = 0.0f;
    for (int n = blockIdx.x * 256 + tid; n < LEN; n += gridDim.x * 256) {
        int p  = n + PADS;
        int tb = p >> 7;
        int k0 = p & (HOPL - 1);
        float s = 0.0f;
        #pragma unroll
        for (int jj = 0; jj < 4; ++jj) {
            int t = tb - jj;
            if (t >= 0 && t < TFR)
                s += d_yf[((size_t)b * TPAD + t) * NFFT + k0 + (jj << 7)];
        }
        float y = s / denom_at(p);
        d_y[(size_t)b * LEN + n] = y;
        m = fmaxf(m, fabsf(y));
    }
    s_red[tid] = m;
    __syncthreads();
    for (int off = 128; off > 0; off >>= 1) {
        if (tid < off) s_red[tid] = fmaxf(s_red[tid], s_red[tid + off]);
        __syncthreads();
    }
    if (tid == 0) atomicMax(&d_maxb[b], __float_as_uint(s_red[0]));
}

// ---------------------------------------------------------------------------
__global__ __launch_bounds__(256) void norm_k(float* __restrict__ out) {
    const int b = blockIdx.y;
    const int n = blockIdx.x * 256 + threadIdx.x;
    if (n >= LEN) return;
    float mx  = __uint_as_float(d_maxb[b]);
    float inv = 1.0f / (mx + 1e-8f);
    out[(size_t)b * LEN + n] = d_y[(size_t)b * LEN + n] * inv;
}

// ---------------------------------------------------------------------------
extern "C" void kernel_launch(void* const* d_in, const int* in_sizes, int n_in,
                              void* d_out, int out_size) {
    (void)in_sizes; (void)n_in; (void)out_size;
    const float* mag   = (const float*)d_in[0];   // [32, 80, 2000]
    const float* noise = (const float*)d_in[1];   // [32, 320000]
    float* out = (float*)d_out;                   // [32, 320000]

    init_tables_k<<<1, 512>>>();
    frame_k<<<dim3(NPAIR, BATCH), 128>>>(mag, noise);
    gather_k<<<dim3(160, BATCH), 256>>>();
    norm_k<<<dim3((LEN + 255) / 256, BATCH), 256>>>(out);
}

// round 3
// speedup vs baseline: 2.0439x; 1.2521x over previous
#include <cuda_runtime.h>
#include <math.h>

#ifndef M_PI
#define M_PI 3.14159265358979323846
#endif

#define NB     80
#define NFFT   512
#define HOPL   128
#define PADS   256
#define NFREQ  257
#define NFRM   2000
#define BATCH  32
#define LEN    320000
#define TFR    2501                 // LEN/HOPL + 1
#define TPAD   2502
#define NPAIR  1251

// ---- static device scratch (allocation-free rule) ----
__device__ float d_win[NFFT];
__device__ float d_win2[NFFT];
__device__ float d_twr[NFFT/2];
__device__ float d_twi[NFFT/2];
__device__ int   d_band[NFREQ];
__device__ float d_yf[(size_t)BATCH * TPAD * NFFT];   // ~164 MB frame outputs
__device__ float d_y[(size_t)BATCH * LEN];            // ~41 MB un-normalized audio
__device__ unsigned int d_maxb[BATCH];

__device__ __forceinline__ int brev9(int p) {
    return (int)(__brev((unsigned)p) >> 23);
}

// ---------------------------------------------------------------------------
__global__ void init_tables_k() {
    __shared__ float s_edges[NB + 1];
    int j = threadIdx.x;

    if (j <= NB) {
        double mel_max = 2595.0 * log10(1.0 + 8000.0 / 700.0);
        double delta   = mel_max / (double)NB;
        double mel     = (j == NB) ? mel_max : (double)j * delta;
        double hz      = 700.0 * (pow(10.0, mel / 2595.0) - 1.0);
        s_edges[j]     = (float)(hz / 8000.0);
    }
    if (j < NFFT) {
        double w = 0.5 * (1.0 - cos(2.0 * M_PI * (double)j / (double)NFFT));
        d_win[j]  = (float)w;
        d_win2[j] = (float)(w * w);
    }
    if (j < NFFT/2) {
        double ang = -2.0 * M_PI * (double)j / (double)NFFT;
        d_twr[j] = (float)cos(ang);
        d_twi[j] = (float)sin(ang);
    }
    if (j < BATCH) d_maxb[j] = 0u;
    __syncthreads();
    if (j < NFREQ) {
        float freq = (float)j / 256.0f;
        int idx = 0;
        #pragma unroll 1
        for (int e = 0; e <= NB; ++e) idx += (s_edges[e] <= freq) ? 1 : 0;  // searchsorted 'right'
        int band = idx - 1;
        d_band[j] = (band >= 0 && band < NB) ? band : -1;
    }
}

// ---------------------------------------------------------------------------
// Fused forward DIF stages (LS, LS-1). 128 threads, one 4-point group each.
// ---------------------------------------------------------------------------
template<int LS>
__device__ __forceinline__ void fwd_fused(float* re, float* im,
                                          const float* twr, const float* twi, int t) {
    const int S  = 1 << LS;
    const int S2 = S >> 1;
    const int j2  = t & (S2 - 1);
    const int blk = t >> (LS - 1);
    const int i   = (blk << (LS + 1)) | j2;

    float ar = re[i],       ai = im[i];
    float br = re[i+S2],    bi = im[i+S2];
    float cr = re[i+S],     ci = im[i+S];
    float dr = re[i+S+S2],  di = im[i+S+S2];

    const int kA = j2 << (8 - LS);
    const int kB = j2 << (9 - LS);
    float wAr = twr[kA], wAi = twi[kA];
    float wBr = twr[kB], wBi = twi[kB];

    // stage A (stride S): pairs (a,c) twiddle W[kA]; (b,d) twiddle W[kA+128] = (wAi,-wAr)
    float t0r = ar + cr, t0i = ai + ci;
    float t1r = ar - cr, t1i = ai - ci;
    float c1r = t1r * wAr - t1i * wAi;
    float c1i = t1r * wAi + t1i * wAr;
    float t2r = br + dr, t2i = bi + di;
    float t3r = br - dr, t3i = bi - di;
    float d1r = t3r * wAi + t3i * wAr;
    float d1i = t3i * wAi - t3r * wAr;

    // stage B (stride S2): pairs (t0,t2) and (c1,d1), twiddle W[kB]
    re[i]      = t0r + t2r;  im[i]      = t0i + t2i;
    float er = t0r - t2r, ei = t0i - t2i;
    re[i+S2]   = er * wBr - ei * wBi;
    im[i+S2]   = er * wBi + ei * wBr;
    re[i+S]    = c1r + d1r;  im[i+S]    = c1i + d1i;
    float fr = c1r - d1r, fi = c1i - d1i;
    re[i+S+S2] = fr * wBr - fi * wBi;
    im[i+S+S2] = fr * wBi + fi * wBr;
}

// ---------------------------------------------------------------------------
// Fused inverse DIT stages (LS, LS+1). 128 threads, one 4-point group each.
// ---------------------------------------------------------------------------
template<int LS>
__device__ __forceinline__ void inv_fused(float* re, float* im,
                                          const float* twr, const float* twi, int t) {
    const int S   = 1 << LS;
    const int j2  = t & (S - 1);
    const int blk = t >> LS;
    const int i   = (blk << (LS + 2)) | j2;

    float ar = re[i],      ai = im[i];
    float br = re[i+S],    bi = im[i+S];
    float cr = re[i+2*S],  ci = im[i+2*S];
    float dr = re[i+3*S],  di = im[i+3*S];

    const int kA = j2 << (8 - LS);
    const int kB = j2 << (7 - LS);
    float wAr = twr[kA], wAi = -twi[kA];   // conj
    float wBr = twr[kB], wBi = -twi[kB];
    float w2r = twi[kB], w2i = twr[kB];    // conj(W[kB+128]) = i*conj(W[kB])

    // stage A (stride S)
    float vbr = br * wAr - bi * wAi, vbi = br * wAi + bi * wAr;
    float a1r = ar + vbr, a1i = ai + vbi;
    float b1r = ar - vbr, b1i = ai - vbi;
    float vdr = dr * wAr - di * wAi, vdi = dr * wAi + di * wAr;
    float c1r = cr + vdr, c1i = ci + vdi;
    float d1r = cr - vdr, d1i = ci - vdi;

    // stage B (stride 2S): pairs (a1,c1) conjW[kB]; (b1,d1) conjW[kB+128]
    float vcr = c1r * wBr - c1i * wBi, vci = c1r * wBi + c1i * wBr;
    re[i]     = a1r + vcr;  im[i]     = a1i + vci;
    re[i+2*S] = a1r - vcr;  im[i+2*S] = a1i - vci;
    float vd2r = d1r * w2r - d1i * w2i, vd2i = d1r * w2i + d1i * w2r;
    re[i+S]   = b1r + vd2r; im[i+S]   = b1i + vd2i;
    re[i+3*S] = b1r - vd2r; im[i+3*S] = b1i - vd2i;
}

// ---------------------------------------------------------------------------
// One block per (frame-pair q, batch b). 128 threads.
// ---------------------------------------------------------------------------
__global__ __launch_bounds__(128) void frame_k(const float* __restrict__ mag,
                                               const float* __restrict__ noise) {
    const int q   = blockIdx.x;
    const int b   = blockIdx.y;
    const int tid = threadIdx.x;
    const int t0  = 2 * q;
    const int t1  = 2 * q + 1;
    const bool t1v = (t1 < TFR);
    const int t1c = t1v ? t1 : (TFR - 1);

    __shared__ __align__(16) float re[NFFT];
    __shared__ __align__(16) float im[NFFT];
    __shared__ float s_twr[NFFT/2], s_twi[NFFT/2];
    __shared__ float s_win[NFFT];
    __shared__ float s_a[NFREQ], s_d[NFREQ];
    __shared__ float s_m0[NB], s_m1[NB];

    // phase 1: tables + interpolated band magnitudes
    #pragma unroll
    for (int r = 0; r < 2; ++r) {
        int k = tid + r * 128;
        s_twr[k] = d_twr[k];
        s_twi[k] = d_twi[k];
    }
    #pragma unroll
    for (int r = 0; r < 4; ++r) {
        int k = tid + r * 128;
        s_win[k] = d_win[k];
    }
    if (tid < NB) {
        const float* mrow = mag + ((size_t)b * NB + tid) * NFRM;
        {
            double pos = (double)t0 * (1999.0 / 2500.0);
            int   i0  = (int)pos;
            float wfr = (float)(pos - (double)i0);
            int   i1  = min(i0 + 1, NFRM - 1);
            s_m0[tid] = mrow[i0] * (1.0f - wfr) + mrow[i1] * wfr;
        }
        {
            double pos = (double)t1c * (1999.0 / 2500.0);
            int   i0  = (int)pos;
            float wfr = (float)(pos - (double)i0);
            int   i1  = min(i0 + 1, NFRM - 1);
            s_m1[tid] = mrow[i0] * (1.0f - wfr) + mrow[i1] * wfr;
        }
    }
    __syncthreads();

    // phase 2: mask coefficients + packed windowed frame load (reflect pad)
    for (int f = tid; f < NFREQ; f += 128) {
        int bd = d_band[f];
        float m0 = (bd >= 0) ? s_m0[bd] : 0.0f;
        float m1 = (bd >= 0) ? s_m1[bd] : 0.0f;
        s_a[f] = 0.5f * (m0 + m1);
        s_d[f] = 0.5f * (m0 - m1);
    }
    {
        const float* nb_ = noise + (size_t)b * LEN;
        int base = t0 * HOPL - PADS;
        #pragma unroll
        for (int r = 0; r < 4; ++r) {
            int jj = tid + r * 128;
            int m0i = base + jj;
            if (m0i < 0)         m0i = -m0i;
            else if (m0i >= LEN) m0i = 2 * LEN - 2 - m0i;
            int m1i = base + HOPL + jj;
            if (m1i < 0)         m1i = -m1i;
            else if (m1i >= LEN) m1i = 2 * LEN - 2 - m1i;
            float w = s_win[jj];
            re[jj] = nb_[m0i] * w;
            im[jj] = nb_[m1i] * w;
        }
    }
    __syncthreads();

    // ---- forward FFT: DIF, fused radix-4 stages (natural -> bitrev) ----
    fwd_fused<8>(re, im, s_twr, s_twi, tid);  __syncthreads();
    fwd_fused<6>(re, im, s_twr, s_twi, tid);  __syncthreads();
    fwd_fused<4>(re, im, s_twr, s_twi, tid);  __syncthreads();
    fwd_fused<2>(re, im, s_twr, s_twi, tid);  __syncthreads();
    {   // last stage ls=0, float4 (twiddle = 1)
        float4 vr = reinterpret_cast<float4*>(re)[tid];
        float4 vi = reinterpret_cast<float4*>(im)[tid];
        float4 or_, oi_;
        or_.x = vr.x + vr.y;  or_.y = vr.x - vr.y;
        or_.z = vr.z + vr.w;  or_.w = vr.z - vr.w;
        oi_.x = vi.x + vi.y;  oi_.y = vi.x - vi.y;
        oi_.z = vi.z + vi.w;  oi_.w = vi.z - vi.w;
        reinterpret_cast<float4*>(re)[tid] = or_;
        reinterpret_cast<float4*>(im)[tid] = oi_;
    }
    __syncthreads();

    // ---- two-frame mask in bitrev layout: W[k] = a*Z[k] + d*conj(Z[N-k]) ----
    {
        float nr[4], ni[4];
        #pragma unroll
        for (int r = 0; r < 4; ++r) {
            int p  = tid + r * 128;
            int k  = brev9(p);
            int p2 = brev9((NFFT - k) & (NFFT - 1));
            int f  = (k <= 256) ? k : NFFT - k;
            float a  = s_a[f];
            float dd = s_d[f];
            nr[r] = a * re[p] + dd * re[p2];
            ni[r] = a * im[p] - dd * im[p2];
        }
        __syncthreads();
        #pragma unroll
        for (int r = 0; r < 4; ++r) {
            int p = tid + r * 128;
            re[p] = nr[r];
            im[p] = ni[r];
        }
    }
    __syncthreads();

    // ---- inverse FFT: DIT, fused radix-4 stages (bitrev -> natural) ----
    {   // fused stages (0,1), float4: twiddles 1 and {1, i}
        float4 vr = reinterpret_cast<float4*>(re)[tid];
        float4 vi = reinterpret_cast<float4*>(im)[tid];
        // stage 0
        float a1r = vr.x + vr.y, a1i = vi.x + vi.y;
        float b1r = vr.x - vr.y, b1i = vi.x - vi.y;
        float c1r = vr.z + vr.w, c1i = vi.z + vi.w;
        float d1r = vr.z - vr.w, d1i = vi.z - vi.w;
        // stage 1: (a1,c1) tw 1; (b1,d1) tw i  (i*(x+iy) = (-y, x))
        float4 or_, oi_;
        or_.x = a1r + c1r;  oi_.x = a1i + c1i;
        or_.z = a1r - c1r;  oi_.z = a1i - c1i;
        float vdr = -d1i, vdi = d1r;
        or_.y = b1r + vdr;  oi_.y = b1i + vdi;
        or_.w = b1r - vdr;  oi_.w = b1i - vdi;
        reinterpret_cast<float4*>(re)[tid] = or_;
        reinterpret_cast<float4*>(im)[tid] = oi_;
    }
    __syncthreads();
    inv_fused<2>(re, im, s_twr, s_twi, tid);  __syncthreads();
    inv_fused<4>(re, im, s_twr, s_twi, tid);  __syncthreads();
    inv_fused<6>(re, im, s_twr, s_twi, tid);  __syncthreads();
    {   // last stage ls=8
        #pragma unroll
        for (int r = 0; r < 2; ++r) {
            int p = tid + r * 128;
            float wr = s_twr[p], wi = -s_twi[p];
            float br = re[p + 256], bi = im[p + 256];
            float vr = br * wr - bi * wi;
            float vi = br * wi + bi * wr;
            float ar = re[p], ai = im[p];
            re[p]       = ar + vr;  im[p]       = ai + vi;
            re[p + 256] = ar - vr;  im[p + 256] = ai - vi;
        }
    }
    __syncthreads();

    // ---- windowed frame outputs, coalesced (y0 = Re, y1 = Im) ----
    {
        const float scale = 1.0f / (float)NFFT;
        float* y0 = d_yf + ((size_t)b * TPAD + t0) * NFFT;
        #pragma unroll
        for (int r = 0; r < 4; ++r) {
            int jj = tid + r * 128;
            y0[jj] = re[jj] * (s_win[jj] * scale);
        }
        if (t1v) {
            float* y1 = d_yf + ((size_t)b * TPAD + t1) * NFFT;
            #pragma unroll
            for (int r = 0; r < 4; ++r) {
                int jj = tid + r * 128;
                y1[jj] = im[jj] * (s_win[jj] * scale);
            }
        }
    }
}

// ---------------------------------------------------------------------------
__device__ __forceinline__ float denom_at(int p) {
    int k0 = p & (HOPL - 1);
    int tb = p >> 7;
    float s = 0.0f;
    #pragma unroll
    for (int jj = 0; jj < 4; ++jj) {
        int tt = tb - jj;
        if (tt >= 0 && tt <= TFR - 1) s += d_win2[k0 + (jj << 7)];
    }
    return (s > 1e-11f) ? s : 1.0f;
}

// ---------------------------------------------------------------------------
__global__ __launch_bounds__(256) void gather_k() {
    const int b   = blockIdx.y;
    const int tid = threadIdx.x;
    __shared__ float s_red[256];
    float m = 0.0f;
    for (int n = blockIdx.x * 256 + tid; n < LEN; n += gridDim.x * 256) {
        int p  = n + PADS;
        int tb = p >> 7;
        int k0 = p & (HOPL - 1);
        float s = 0.0f;
        #pragma unroll
        for (int jj = 0; jj < 4; ++jj) {
            int t = tb - jj;
            if (t >= 0 && t < TFR)
                s += d_yf[((size_t)b * TPAD + t) * NFFT + k0 + (jj << 7)];
        }
        float y = s / denom_at(p);
        d_y[(size_t)b * LEN + n] = y;
        m = fmaxf(m, fabsf(y));
    }
    s_red[tid] = m;
    __syncthreads();
    for (int off = 128; off > 0; off >>= 1) {
        if (tid < off) s_red[tid] = fmaxf(s_red[tid], s_red[tid + off]);
        __syncthreads();
    }
    if (tid == 0) atomicMax(&d_maxb[b], __float_as_uint(s_red[0]));
}

// ---------------------------------------------------------------------------
__global__ __launch_bounds__(256) void norm_k(float* __restrict__ out) {
    const int b = blockIdx.y;
    const int n4 = blockIdx.x * 256 + threadIdx.x;
    if (n4 >= LEN / 4) return;
    float mx  = __uint_as_float(d_maxb[b]);
    float inv = 1.0f / (mx + 1e-8f);
    const float4* src = reinterpret_cast<const float4*>(d_y + (size_t)b * LEN);
    float4* dst = reinterpret_cast<float4*>(out + (size_t)b * LEN);
    float4 v = src[n4];
    v.x *= inv; v.y *= inv; v.z *= inv; v.w *= inv;
    dst[n4] = v;
}

// ---------------------------------------------------------------------------
extern "C" void kernel_launch(void* const* d_in, const int* in_sizes, int n_in,
                              void* d_out, int out_size) {
    (void)in_sizes; (void)n_in; (void)out_size;
    const float* mag   = (const float*)d_in[0];   // [32, 80, 2000]
    const float* noise = (const float*)d_in[1];   // [32, 320000]
    float* out = (float*)d_out;                   // [32, 320000]

    init_tables_k<<<1, 512>>>();
    frame_k<<<dim3(NPAIR, BATCH), 128>>>(mag, noise);
    gather_k<<<dim3(160, BATCH), 256>>>();
    norm_k<<<dim3((LEN / 4 + 255) / 256, BATCH), 256>>>(out);
}

// round 4
// speedup vs baseline: 3.2409x; 1.5857x over previous
#include <cuda_runtime.h>
#include <math.h>

#ifndef M_PI
#define M_PI 3.14159265358979323846
#endif

#define NB     80
#define NFFT   512
#define HOPL   128
#define PADS   256
#define NFREQ  257
#define NFRM   2000
#define BATCH  32
#define LEN    320000
#define TFR    2501
#define TPAD   2502
#define NPAIR  1251

// padded shared index: 4 floats of pad per 32 (keeps float4 groups aligned)
__device__ __forceinline__ int IDX(int i)  { return i + ((i >> 5) << 2); }
__device__ __forceinline__ int VIDX(int t) { return t + (t >> 3); }        // float4 index for group t
#define SPAD (NFFT + (NFFT/32)*4)   // 576

// ---- static device scratch ----
__device__ float d_win[NFFT];
__device__ float d_win2[NFFT];
__device__ int   d_band[NFREQ];
__device__ float d_T1r[256],  d_T1i[256];   // W^j
__device__ float d_T2r[64],   d_T2i[64];    // W^{2j}
__device__ float d_T4r[32],   d_T4i[32];    // W^{4j}
__device__ float d_T8r[16],   d_T8i[16];    // W^{8j}
__device__ float d_T16r[8],   d_T16i[8];    // W^{16j}
__device__ float d_T32r[4],   d_T32i[4];    // W^{32j}
__device__ float d_yf[(size_t)BATCH * TPAD * NFFT];   // ~164 MB frame outputs
__device__ unsigned int d_maxb[BATCH];

__device__ __forceinline__ int brev9(int p) {
    return (int)(__brev((unsigned)p) >> 23);
}

// ---------------------------------------------------------------------------
__global__ void init_tables_k() {
    __shared__ float s_edges[NB + 1];
    int j = threadIdx.x;

    if (j <= NB) {
        double mel_max = 2595.0 * log10(1.0 + 8000.0 / 700.0);
        double delta   = mel_max / (double)NB;
        double mel     = (j == NB) ? mel_max : (double)j * delta;
        double hz      = 700.0 * (pow(10.0, mel / 2595.0) - 1.0);
        s_edges[j]     = (float)(hz / 8000.0);
    }
    if (j < NFFT) {
        double w = 0.5 * (1.0 - cos(2.0 * M_PI * (double)j / (double)NFFT));
        d_win[j]  = (float)w;
        d_win2[j] = (float)(w * w);
    }
    // twiddle tables W^{s*j} = exp(-2*pi*i*s*j/512)
    if (j < 256) { double a = -2.0*M_PI*(double)j/512.0;      d_T1r[j]=(float)cos(a); d_T1i[j]=(float)sin(a); }
    if (j < 64)  { double a = -2.0*M_PI*(double)(2*j)/512.0;  d_T2r[j]=(float)cos(a); d_T2i[j]=(float)sin(a); }
    if (j < 32)  { double a = -2.0*M_PI*(double)(4*j)/512.0;  d_T4r[j]=(float)cos(a); d_T4i[j]=(float)sin(a); }
    if (j < 16)  { double a = -2.0*M_PI*(double)(8*j)/512.0;  d_T8r[j]=(float)cos(a); d_T8i[j]=(float)sin(a); }
    if (j < 8)   { double a = -2.0*M_PI*(double)(16*j)/512.0; d_T16r[j]=(float)cos(a); d_T16i[j]=(float)sin(a); }
    if (j < 4)   { double a = -2.0*M_PI*(double)(32*j)/512.0; d_T32r[j]=(float)cos(a); d_T32i[j]=(float)sin(a); }
    if (j < BATCH) d_maxb[j] = 0u;
    __syncthreads();
    if (j < NFREQ) {
        float freq = (float)j / 256.0f;
        int idx = 0;
        #pragma unroll 1
        for (int e = 0; e <= NB; ++e) idx += (s_edges[e] <= freq) ? 1 : 0;  // searchsorted 'right'
        int band = idx - 1;
        d_band[j] = (band >= 0 && band < NB) ? band : -1;
    }
}

// ---------------------------------------------------------------------------
// Generic fused forward DIF stages (LS, LS-1). Stage-A twiddle from dense
// table (index j2), stage-B twiddle = square of stage-A.
// ---------------------------------------------------------------------------
template<int LS>
__device__ __forceinline__ void fwd_pass(float* re, float* im,
                                         const float* Tr, const float* Ti, int t) {
    const int S  = 1 << LS;
    const int S2 = S >> 1;
    const int j2  = t & (S2 - 1);
    const int blk = t >> (LS - 1);
    const int i   = (blk << (LS + 1)) | j2;

    float ar = re[IDX(i)],      ai = im[IDX(i)];
    float br = re[IDX(i+S2)],   bi = im[IDX(i+S2)];
    float cr = re[IDX(i+S)],    ci = im[IDX(i+S)];
    float dr = re[IDX(i+S+S2)], di = im[IDX(i+S+S2)];

    float wAr = __ldg(Tr + j2), wAi = __ldg(Ti + j2);
    float wBr = wAr*wAr - wAi*wAi, wBi = 2.0f*wAr*wAi;

    float t0r = ar + cr, t0i = ai + ci;
    float t1r = ar - cr, t1i = ai - ci;
    float c1r = t1r * wAr - t1i * wAi;
    float c1i = t1r * wAi + t1i * wAr;
    float t2r = br + dr, t2i = bi + di;
    float t3r = br - dr, t3i = bi - di;
    float d1r = t3r * wAi + t3i * wAr;
    float d1i = t3i * wAi - t3r * wAr;

    re[IDX(i)]      = t0r + t2r;  im[IDX(i)]      = t0i + t2i;
    float er = t0r - t2r, ei = t0i - t2i;
    re[IDX(i+S2)]   = er * wBr - ei * wBi;
    im[IDX(i+S2)]   = er * wBi + ei * wBr;
    re[IDX(i+S)]    = c1r + d1r;  im[IDX(i+S)]    = c1i + d1i;
    float fr = c1r - d1r, fi = c1i - d1i;
    re[IDX(i+S+S2)] = fr * wBr - fi * wBi;
    im[IDX(i+S+S2)] = fr * wBi + fi * wBr;
}

// forward stages (2,1) with constant twiddles (W^{64j2}, squared)
__device__ __forceinline__ void fwd_p2(float* re, float* im, int t) {
    const int j2 = t & 1;
    const int blk = t >> 1;
    const int i = (blk << 3) | j2;
    const float C = 0.70710678118654752f;

    float ar = re[IDX(i)],   ai = im[IDX(i)];
    float br = re[IDX(i+2)], bi = im[IDX(i+2)];
    float cr = re[IDX(i+4)], ci = im[IDX(i+4)];
    float dr = re[IDX(i+6)], di = im[IDX(i+6)];

    float wAr = j2 ? C : 1.0f, wAi = j2 ? -C : 0.0f;
    float wBr = wAr*wAr - wAi*wAi, wBi = 2.0f*wAr*wAi;

    float t0r = ar + cr, t0i = ai + ci;
    float t1r = ar - cr, t1i = ai - ci;
    float c1r = t1r * wAr - t1i * wAi;
    float c1i = t1r * wAi + t1i * wAr;
    float t2r = br + dr, t2i = bi + di;
    float t3r = br - dr, t3i = bi - di;
    float d1r = t3r * wAi + t3i * wAr;
    float d1i = t3i * wAi - t3r * wAr;

    re[IDX(i)]   = t0r + t2r;  im[IDX(i)]   = t0i + t2i;
    float er = t0r - t2r, ei = t0i - t2i;
    re[IDX(i+2)] = er * wBr - ei * wBi;
    im[IDX(i+2)] = er * wBi + ei * wBr;
    re[IDX(i+4)] = c1r + d1r;  im[IDX(i+4)] = c1i + d1i;
    float fr = c1r - d1r, fi = c1i - d1i;
    re[IDX(i+6)] = fr * wBr - fi * wBi;
    im[IDX(i+6)] = fr * wBi + fi * wBr;
}

// ---------------------------------------------------------------------------
// Generic fused inverse DIT stages (LS, LS+1). Stage-B (outer) conj twiddle
// from dense table; stage-A = square; 3rd factor w2 = i*wB.
// ---------------------------------------------------------------------------
template<int LS>
__device__ __forceinline__ void inv_pass(float* re, float* im,
                                         const float* Tr, const float* Ti, int t) {
    const int S   = 1 << LS;
    const int j2  = t & (S - 1);
    const int blk = t >> LS;
    const int i   = (blk << (LS + 2)) | j2;

    float ar = re[IDX(i)],      ai = im[IDX(i)];
    float br = re[IDX(i+S)],    bi = im[IDX(i+S)];
    float cr = re[IDX(i+2*S)],  ci = im[IDX(i+2*S)];
    float dr = re[IDX(i+3*S)],  di = im[IDX(i+3*S)];

    float wBr = __ldg(Tr + j2), wBi = -__ldg(Ti + j2);
    float wAr = wBr*wBr - wBi*wBi, wAi = 2.0f*wBr*wBi;
    float w2r = -wBi, w2i = wBr;

    float vbr = br * wAr - bi * wAi, vbi = br * wAi + bi * wAr;
    float a1r = ar + vbr, a1i = ai + vbi;
    float b1r = ar - vbr, b1i = ai - vbi;
    float vdr = dr * wAr - di * wAi, vdi = dr * wAi + di * wAr;
    float c1r = cr + vdr, c1i = ci + vdi;
    float d1r = cr - vdr, d1i = ci - vdi;

    float vcr = c1r * wBr - c1i * wBi, vci = c1r * wBi + c1i * wBr;
    re[IDX(i)]     = a1r + vcr;  im[IDX(i)]     = a1i + vci;
    re[IDX(i+2*S)] = a1r - vcr;  im[IDX(i+2*S)] = a1i - vci;
    float vd2r = d1r * w2r - d1i * w2i, vd2i = d1r * w2i + d1i * w2r;
    re[IDX(i+S)]   = b1r + vd2r; im[IDX(i+S)]   = b1i + vd2i;
    re[IDX(i+3*S)] = b1r - vd2r; im[IDX(i+3*S)] = b1i - vd2i;
}

// ---------------------------------------------------------------------------
// One block per (frame-pair q, batch b). 128 threads.
// ---------------------------------------------------------------------------
__global__ __launch_bounds__(128) void frame_k(const float* __restrict__ mag,
                                               const float* __restrict__ noise) {
    const int q   = blockIdx.x;
    const int b   = blockIdx.y;
    const int tid = threadIdx.x;
    const int t0  = 2 * q;
    const int t1  = 2 * q + 1;
    const bool t1v = (t1 < TFR);
    const int t1c = t1v ? t1 : (TFR - 1);

    __shared__ __align__(16) float re[SPAD];
    __shared__ __align__(16) float im[SPAD];
    __shared__ float s_a[NFREQ], s_d[NFREQ];
    __shared__ float s_m0[NB], s_m1[NB];

    // phase 0: band magnitudes + fused [global load -> fwd stages (8,7)]
    if (tid < NB) {
        const float* mrow = mag + ((size_t)b * NB + tid) * NFRM;
        {
            double pos = (double)t0 * (1999.0 / 2500.0);
            int   i0  = (int)pos;
            float wfr = (float)(pos - (double)i0);
            int   i1  = min(i0 + 1, NFRM - 1);
            s_m0[tid] = mrow[i0] * (1.0f - wfr) + mrow[i1] * wfr;
        }
        {
            double pos = (double)t1c * (1999.0 / 2500.0);
            int   i0  = (int)pos;
            float wfr = (float)(pos - (double)i0);
            int   i1  = min(i0 + 1, NFRM - 1);
            s_m1[tid] = mrow[i0] * (1.0f - wfr) + mrow[i1] * wfr;
        }
    }
    {
        const float* nb_ = noise + (size_t)b * LEN;
        const int base = t0 * HOPL - PADS;
        float xr[4], xi[4];
        #pragma unroll
        for (int m = 0; m < 4; ++m) {
            int jj = tid + m * 128;
            int m0i = base + jj;
            if (m0i < 0)         m0i = -m0i;
            else if (m0i >= LEN) m0i = 2 * LEN - 2 - m0i;
            int m1i = base + HOPL + jj;
            if (m1i < 0)         m1i = -m1i;
            else if (m1i >= LEN) m1i = 2 * LEN - 2 - m1i;
            float w = __ldg(&d_win[jj]);
            xr[m] = nb_[m0i] * w;
            xi[m] = nb_[m1i] * w;
        }
        // fused fwd stages (8,7): points tid, tid+128, tid+256, tid+384
        float wAr = __ldg(&d_T1r[tid]), wAi = __ldg(&d_T1i[tid]);
        float wBr = wAr*wAr - wAi*wAi,  wBi = 2.0f*wAr*wAi;

        float t0r = xr[0] + xr[2], t0i = xi[0] + xi[2];
        float t1r = xr[0] - xr[2], t1i = xi[0] - xi[2];
        float c1r = t1r * wAr - t1i * wAi;
        float c1i = t1r * wAi + t1i * wAr;
        float t2r = xr[1] + xr[3], t2i = xi[1] + xi[3];
        float t3r = xr[1] - xr[3], t3i = xi[1] - xi[3];
        float d1r = t3r * wAi + t3i * wAr;
        float d1i = t3i * wAi - t3r * wAr;

        re[IDX(tid)]     = t0r + t2r;  im[IDX(tid)]     = t0i + t2i;
        float er = t0r - t2r, ei = t0i - t2i;
        re[IDX(tid+128)] = er * wBr - ei * wBi;
        im[IDX(tid+128)] = er * wBi + ei * wBr;
        re[IDX(tid+256)] = c1r + d1r;  im[IDX(tid+256)] = c1i + d1i;
        float fr = c1r - d1r, fi = c1i - d1i;
        re[IDX(tid+384)] = fr * wBr - fi * wBi;
        im[IDX(tid+384)] = fr * wBi + fi * wBr;
    }
    __syncthreads();

    // fwd stages (6,5) + mask coefficient fill
    fwd_pass<6>(re, im, d_T4r, d_T4i, tid);
    for (int f = tid; f < NFREQ; f += 128) {
        int bd = d_band[f];
        float m0 = (bd >= 0) ? s_m0[bd] : 0.0f;
        float m1 = (bd >= 0) ? s_m1[bd] : 0.0f;
        s_a[f] = 0.5f * (m0 + m1);
        s_d[f] = 0.5f * (m0 - m1);
    }
    __syncthreads();
    fwd_pass<4>(re, im, d_T16r, d_T16i, tid);
    __syncthreads();
    fwd_p2(re, im, tid);
    __syncthreads();

    // fwd stage (0) in float4 registers; keep Z in regs, also publish to shared
    float zr[4], zi[4];
    {
        float4 vr = reinterpret_cast<float4*>(re)[VIDX(tid)];
        float4 vi = reinterpret_cast<float4*>(im)[VIDX(tid)];
        zr[0] = vr.x + vr.y;  zr[1] = vr.x - vr.y;
        zr[2] = vr.z + vr.w;  zr[3] = vr.z - vr.w;
        zi[0] = vi.x + vi.y;  zi[1] = vi.x - vi.y;
        zi[2] = vi.z + vi.w;  zi[3] = vi.z - vi.w;
        float4 or_, oi_;
        or_.x = zr[0]; or_.y = zr[1]; or_.z = zr[2]; or_.w = zr[3];
        oi_.x = zi[0]; oi_.y = zi[1]; oi_.z = zi[2]; oi_.w = zi[3];
        reinterpret_cast<float4*>(re)[VIDX(tid)] = or_;
        reinterpret_cast<float4*>(im)[VIDX(tid)] = oi_;
    }
    __syncthreads();

    // fused: two-frame mask + inverse stages (0,1), in registers
    {
        float wr_[4], wi_[4];
        #pragma unroll
        for (int c = 0; c < 4; ++c) {
            int p  = 4 * tid + c;
            int k  = brev9(p);
            int p2 = brev9((NFFT - k) & (NFFT - 1));
            int f  = (k <= 256) ? k : NFFT - k;
            float a  = s_a[f];
            float dd = s_d[f];
            wr_[c] = a * zr[c] + dd * re[IDX(p2)];
            wi_[c] = a * zi[c] - dd * im[IDX(p2)];
        }
        // inverse stages (0,1)
        float a1r = wr_[0] + wr_[1], a1i = wi_[0] + wi_[1];
        float b1r = wr_[0] - wr_[1], b1i = wi_[0] - wi_[1];
        float c1r = wr_[2] + wr_[3], c1i = wi_[2] + wi_[3];
        float d1r = wr_[2] - wr_[3], d1i = wi_[2] - wi_[3];
        float4 or_, oi_;
        or_.x = a1r + c1r;  oi_.x = a1i + c1i;
        or_.z = a1r - c1r;  oi_.z = a1i - c1i;
        float vdr = -d1i, vdi = d1r;
        or_.y = b1r + vdr;  oi_.y = b1i + vdi;
        or_.w = b1r - vdr;  oi_.w = b1i - vdi;
        __syncthreads();   // everyone done reading partners before overwrite
        reinterpret_cast<float4*>(re)[VIDX(tid)] = or_;
        reinterpret_cast<float4*>(im)[VIDX(tid)] = oi_;
    }
    __syncthreads();

    inv_pass<2>(re, im, d_T32r, d_T32i, tid);  __syncthreads();
    inv_pass<4>(re, im, d_T8r,  d_T8i,  tid);  __syncthreads();
    inv_pass<6>(re, im, d_T2r,  d_T2i,  tid);  __syncthreads();

    // fused: inverse stage (8) + windowed global store
    {
        const float scale = 1.0f / (float)NFFT;
        float* y0 = d_yf + ((size_t)b * TPAD + t0) * NFFT;
        float* y1 = d_yf + ((size_t)b * TPAD + t1) * NFFT;
        #pragma unroll
        for (int r = 0; r < 2; ++r) {
            int p = tid + r * 128;
            float wr = __ldg(&d_T1r[p]), wi = -__ldg(&d_T1i[p]);
            float ar = re[IDX(p)],     ai = im[IDX(p)];
            float br = re[IDX(p+256)], bi = im[IDX(p+256)];
            float vr = br * wr - bi * wi;
            float vi = br * wi + bi * wr;
            float wlo = __ldg(&d_win[p])     * scale;
            float whi = __ldg(&d_win[p+256]) * scale;
            y0[p]       = (ar + vr) * wlo;
            y0[p + 256] = (ar - vr) * whi;
            if (t1v) {
                y1[p]       = (ai + vi) * wlo;
                y1[p + 256] = (ai - vi) * whi;
            }
        }
    }
}

// ---------------------------------------------------------------------------
__device__ __forceinline__ float denom_at(int p) {
    int k0 = p & (HOPL - 1);
    int tb = p >> 7;
    float s = 0.0f;
    #pragma unroll
    for (int jj = 0; jj < 4; ++jj) {
        int tt = tb - jj;
        if (tt >= 0 && tt <= TFR - 1) s += d_win2[k0 + (jj << 7)];
    }
    return (s > 1e-11f) ? s : 1.0f;
}

// ---------------------------------------------------------------------------
// OLA gather (<=4 frames/sample) -> writes un-normalized audio to OUT,
// fused per-batch max reduction.
// ---------------------------------------------------------------------------
__global__ __launch_bounds__(256) void gather_k(float* __restrict__ out) {
    const int b   = blockIdx.y;
    const int tid = threadIdx.x;
    __shared__ float s_red[256];
    float m = 0.0f;
    for (int n = blockIdx.x * 256 + tid; n < LEN; n += gridDim.x * 256) {
        int p  = n + PADS;
        int tb = p >> 7;
        int k0 = p & (HOPL - 1);
        float s = 0.0f;
        #pragma unroll
        for (int jj = 0; jj < 4; ++jj) {
            int t = tb - jj;
            if (t >= 0 && t < TFR)
                s += d_yf[((size_t)b * TPAD + t) * NFFT + k0 + (jj << 7)];
        }
        float y = s / denom_at(p);
        out[(size_t)b * LEN + n] = y;
        m = fmaxf(m, fabsf(y));
    }
    s_red[tid] = m;
    __syncthreads();
    for (int off = 128; off > 0; off >>= 1) {
        if (tid < off) s_red[tid] = fmaxf(s_red[tid], s_red[tid + off]);
        __syncthreads();
    }
    if (tid == 0) atomicMax(&d_maxb[b], __float_as_uint(s_red[0]));
}

// ---------------------------------------------------------------------------
__global__ __launch_bounds__(256) void norm_k(float* __restrict__ out) {
    const int b  = blockIdx.y;
    const int n4 = blockIdx.x * 256 + threadIdx.x;
    if (n4 >= LEN / 4) return;
    float mx  = __uint_as_float(d_maxb[b]);
    float inv = 1.0f / (mx + 1e-8f);
    float4* ptr = reinterpret_cast<float4*>(out + (size_t)b * LEN);
    float4 v = ptr[n4];
    v.x *= inv; v.y *= inv; v.z *= inv; v.w *= inv;
    ptr[n4] = v;
}

// ---------------------------------------------------------------------------
extern "C" void kernel_launch(void* const* d_in, const int* in_sizes, int n_in,
                              void* d_out, int out_size) {
    (void)in_sizes; (void)n_in; (void)out_size;
    const float* mag   = (const float*)d_in[0];   // [32, 80, 2000]
    const float* noise = (const float*)d_in[1];   // [32, 320000]
    float* out = (float*)d_out;                   // [32, 320000]

    init_tables_k<<<1, 512>>>();
    frame_k<<<dim3(NPAIR, BATCH), 128>>>(mag, noise);
    gather_k<<<dim3(160, BATCH), 256>>>(out);
    norm_k<<<dim3((LEN / 4 + 255) / 256, BATCH), 256>>>(out);
}

// round 5
// speedup vs baseline: 3.3861x; 1.0448x over previous
#include <cuda_runtime.h>
#include <cuda_fp16.h>
#include <math.h>

#ifndef M_PI
#define M_PI 3.14159265358979323846
#endif

#define NB     80
#define NFFT   512
#define HOPL   128
#define PADS   256
#define NFREQ  257
#define NFRM   2000
#define BATCH  32
#define LEN    320000
#define TFR    2501
#define TPAD   2502
#define NPAIR  1251

// padded shared index: 4 floats of pad per 32 (keeps float4 groups aligned)
__device__ __forceinline__ int IDX(int i)  { return i + ((i >> 5) << 2); }
__device__ __forceinline__ int VIDX(int t) { return t + (t >> 3); }        // float4 index for group t
#define SPAD (NFFT + (NFFT/32)*4)   // 576

// ---- static device scratch ----
__device__ float d_win[NFFT];
__device__ float d_win2[NFFT];
__device__ int   d_band[NFREQ];
__device__ float d_T1r[256],  d_T1i[256];   // W^j
__device__ float d_T2r[64],   d_T2i[64];    // W^{2j}
__device__ float d_T4r[32],   d_T4i[32];    // W^{4j}
__device__ float d_T8r[16],   d_T8i[16];    // W^{8j}
__device__ float d_T16r[8],   d_T16i[8];    // W^{16j}
__device__ float d_T32r[4],   d_T32i[4];    // W^{32j}
__device__ __half d_yf[(size_t)BATCH * TPAD * NFFT];  // ~82 MB frame outputs (fp16)
__device__ unsigned int d_maxb[BATCH];

__device__ __forceinline__ int brev9(int p) {
    return (int)(__brev((unsigned)p) >> 23);
}

// ---------------------------------------------------------------------------
__global__ void init_tables_k() {
    __shared__ float s_edges[NB + 1];
    int j = threadIdx.x;

    if (j <= NB) {
        double mel_max = 2595.0 * log10(1.0 + 8000.0 / 700.0);
        double delta   = mel_max / (double)NB;
        double mel     = (j == NB) ? mel_max : (double)j * delta;
        double hz      = 700.0 * (pow(10.0, mel / 2595.0) - 1.0);
        s_edges[j]     = (float)(hz / 8000.0);
    }
    if (j < NFFT) {
        double w = 0.5 * (1.0 - cos(2.0 * M_PI * (double)j / (double)NFFT));
        d_win[j]  = (float)w;
        d_win2[j] = (float)(w * w);
    }
    if (j < 256) { double a = -2.0*M_PI*(double)j/512.0;      d_T1r[j]=(float)cos(a); d_T1i[j]=(float)sin(a); }
    if (j < 64)  { double a = -2.0*M_PI*(double)(2*j)/512.0;  d_T2r[j]=(float)cos(a); d_T2i[j]=(float)sin(a); }
    if (j < 32)  { double a = -2.0*M_PI*(double)(4*j)/512.0;  d_T4r[j]=(float)cos(a); d_T4i[j]=(float)sin(a); }
    if (j < 16)  { double a = -2.0*M_PI*(double)(8*j)/512.0;  d_T8r[j]=(float)cos(a); d_T8i[j]=(float)sin(a); }
    if (j < 8)   { double a = -2.0*M_PI*(double)(16*j)/512.0; d_T16r[j]=(float)cos(a); d_T16i[j]=(float)sin(a); }
    if (j < 4)   { double a = -2.0*M_PI*(double)(32*j)/512.0; d_T32r[j]=(float)cos(a); d_T32i[j]=(float)sin(a); }
    if (j < BATCH) d_maxb[j] = 0u;
    __syncthreads();
    if (j < NFREQ) {
        float freq = (float)j / 256.0f;
        int idx = 0;
        #pragma unroll 1
        for (int e = 0; e <= NB; ++e) idx += (s_edges[e] <= freq) ? 1 : 0;  // searchsorted 'right'
        int band = idx - 1;
        d_band[j] = (band >= 0 && band < NB) ? band : -1;
    }
}

// ---------------------------------------------------------------------------
template<int LS>
__device__ __forceinline__ void fwd_pass(float* re, float* im,
                                         const float* Tr, const float* Ti, int t) {
    const int S  = 1 << LS;
    const int S2 = S >> 1;
    const int j2  = t & (S2 - 1);
    const int blk = t >> (LS - 1);
    const int i   = (blk << (LS + 1)) | j2;

    float ar = re[IDX(i)],      ai = im[IDX(i)];
    float br = re[IDX(i+S2)],   bi = im[IDX(i+S2)];
    float cr = re[IDX(i+S)],    ci = im[IDX(i+S)];
    float dr = re[IDX(i+S+S2)], di = im[IDX(i+S+S2)];

    float wAr = __ldg(Tr + j2), wAi = __ldg(Ti + j2);
    float wBr = wAr*wAr - wAi*wAi, wBi = 2.0f*wAr*wAi;

    float t0r = ar + cr, t0i = ai + ci;
    float t1r = ar - cr, t1i = ai - ci;
    float c1r = t1r * wAr - t1i * wAi;
    float c1i = t1r * wAi + t1i * wAr;
    float t2r = br + dr, t2i = bi + di;
    float t3r = br - dr, t3i = bi - di;
    float d1r = t3r * wAi + t3i * wAr;
    float d1i = t3i * wAi - t3r * wAr;

    re[IDX(i)]      = t0r + t2r;  im[IDX(i)]      = t0i + t2i;
    float er = t0r - t2r, ei = t0i - t2i;
    re[IDX(i+S2)]   = er * wBr - ei * wBi;
    im[IDX(i+S2)]   = er * wBi + ei * wBr;
    re[IDX(i+S)]    = c1r + d1r;  im[IDX(i+S)]    = c1i + d1i;
    float fr = c1r - d1r, fi = c1i - d1i;
    re[IDX(i+S+S2)] = fr * wBr - fi * wBi;
    im[IDX(i+S+S2)] = fr * wBi + fi * wBr;
}

// forward stages (2,1) with constant twiddles
__device__ __forceinline__ void fwd_p2(float* re, float* im, int t) {
    const int j2 = t & 1;
    const int blk = t >> 1;
    const int i = (blk << 3) | j2;
    const float C = 0.70710678118654752f;

    float ar = re[IDX(i)],   ai = im[IDX(i)];
    float br = re[IDX(i+2)], bi = im[IDX(i+2)];
    float cr = re[IDX(i+4)], ci = im[IDX(i+4)];
    float dr = re[IDX(i+6)], di = im[IDX(i+6)];

    float wAr = j2 ? C : 1.0f, wAi = j2 ? -C : 0.0f;
    float wBr = wAr*wAr - wAi*wAi, wBi = 2.0f*wAr*wAi;

    float t0r = ar + cr, t0i = ai + ci;
    float t1r = ar - cr, t1i = ai - ci;
    float c1r = t1r * wAr - t1i * wAi;
    float c1i = t1r * wAi + t1i * wAr;
    float t2r = br + dr, t2i = bi + di;
    float t3r = br - dr, t3i = bi - di;
    float d1r = t3r * wAi + t3i * wAr;
    float d1i = t3i * wAi - t3r * wAr;

    re[IDX(i)]   = t0r + t2r;  im[IDX(i)]   = t0i + t2i;
    float er = t0r - t2r, ei = t0i - t2i;
    re[IDX(i+2)] = er * wBr - ei * wBi;
    im[IDX(i+2)] = er * wBi + ei * wBr;
    re[IDX(i+4)] = c1r + d1r;  im[IDX(i+4)] = c1i + d1i;
    float fr = c1r - d1r, fi = c1i - d1i;
    re[IDX(i+6)] = fr * wBr - fi * wBi;
    im[IDX(i+6)] = fr * wBi + fi * wBr;
}

// ---------------------------------------------------------------------------
template<int LS>
__device__ __forceinline__ void inv_pass(float* re, float* im,
                                         const float* Tr, const float* Ti, int t) {
    const int S   = 1 << LS;
    const int j2  = t & (S - 1);
    const int blk = t >> LS;
    const int i   = (blk << (LS + 2)) | j2;

    float ar = re[IDX(i)],      ai = im[IDX(i)];
    float br = re[IDX(i+S)],    bi = im[IDX(i+S)];
    float cr = re[IDX(i+2*S)],  ci = im[IDX(i+2*S)];
    float dr = re[IDX(i+3*S)],  di = im[IDX(i+3*S)];

    float wBr = __ldg(Tr + j2), wBi = -__ldg(Ti + j2);
    float wAr = wBr*wBr - wBi*wBi, wAi = 2.0f*wBr*wBi;
    float w2r = -wBi, w2i = wBr;

    float vbr = br * wAr - bi * wAi, vbi = br * wAi + bi * wAr;
    float a1r = ar + vbr, a1i = ai + vbi;
    float b1r = ar - vbr, b1i = ai - vbi;
    float vdr = dr * wAr - di * wAi, vdi = dr * wAi + di * wAr;
    float c1r = cr + vdr, c1i = ci + vdi;
    float d1r = cr - vdr, d1i = ci - vdi;

    float vcr = c1r * wBr - c1i * wBi, vci = c1r * wBi + c1i * wBr;
    re[IDX(i)]     = a1r + vcr;  im[IDX(i)]     = a1i + vci;
    re[IDX(i+2*S)] = a1r - vcr;  im[IDX(i+2*S)] = a1i - vci;
    float vd2r = d1r * w2r - d1i * w2i, vd2i = d1r * w2i + d1i * w2r;
    re[IDX(i+S)]   = b1r + vd2r; im[IDX(i+S)]   = b1i + vd2i;
    re[IDX(i+3*S)] = b1r - vd2r; im[IDX(i+3*S)] = b1i - vd2i;
}

// ---------------------------------------------------------------------------
__global__ __launch_bounds__(128) void frame_k(const float* __restrict__ mag,
                                               const float* __restrict__ noise) {
    const int q   = blockIdx.x;
    const int b   = blockIdx.y;
    const int tid = threadIdx.x;
    const int t0  = 2 * q;
    const int t1  = 2 * q + 1;
    const bool t1v = (t1 < TFR);
    const int t1c = t1v ? t1 : (TFR - 1);

    __shared__ __align__(16) float re[SPAD];
    __shared__ __align__(16) float im[SPAD];
    __shared__ float s_a[NFREQ], s_d[NFREQ];
    __shared__ float s_m0[NB], s_m1[NB];

    if (tid < NB) {
        const float* mrow = mag + ((size_t)b * NB + tid) * NFRM;
        {
            double pos = (double)t0 * (1999.0 / 2500.0);
            int   i0  = (int)pos;
            float wfr = (float)(pos - (double)i0);
            int   i1  = min(i0 + 1, NFRM - 1);
            s_m0[tid] = mrow[i0] * (1.0f - wfr) + mrow[i1] * wfr;
        }
        {
            double pos = (double)t1c * (1999.0 / 2500.0);
            int   i0  = (int)pos;
            float wfr = (float)(pos - (double)i0);
            int   i1  = min(i0 + 1, NFRM - 1);
            s_m1[tid] = mrow[i0] * (1.0f - wfr) + mrow[i1] * wfr;
        }
    }
    {
        const float* nb_ = noise + (size_t)b * LEN;
        const int base = t0 * HOPL - PADS;
        float xr[4], xi[4];
        #pragma unroll
        for (int m = 0; m < 4; ++m) {
            int jj = tid + m * 128;
            int m0i = base + jj;
            if (m0i < 0)         m0i = -m0i;
            else if (m0i >= LEN) m0i = 2 * LEN - 2 - m0i;
            int m1i = base + HOPL + jj;
            if (m1i < 0)         m1i = -m1i;
            else if (m1i >= LEN) m1i = 2 * LEN - 2 - m1i;
            float w = __ldg(&d_win[jj]);
            xr[m] = nb_[m0i] * w;
            xi[m] = nb_[m1i] * w;
        }
        float wAr = __ldg(&d_T1r[tid]), wAi = __ldg(&d_T1i[tid]);
        float wBr = wAr*wAr - wAi*wAi,  wBi = 2.0f*wAr*wAi;

        float t0r = xr[0] + xr[2], t0i = xi[0] + xi[2];
        float t1r = xr[0] - xr[2], t1i = xi[0] - xi[2];
        float c1r = t1r * wAr - t1i * wAi;
        float c1i = t1r * wAi + t1i * wAr;
        float t2r = xr[1] + xr[3], t2i = xi[1] + xi[3];
        float t3r = xr[1] - xr[3], t3i = xi[1] - xi[3];
        float d1r = t3r * wAi + t3i * wAr;
        float d1i = t3i * wAi - t3r * wAr;

        re[IDX(tid)]     = t0r + t2r;  im[IDX(tid)]     = t0i + t2i;
        float er = t0r - t2r, ei = t0i - t2i;
        re[IDX(tid+128)] = er * wBr - ei * wBi;
        im[IDX(tid+128)] = er * wBi + ei * wBr;
        re[IDX(tid+256)] = c1r + d1r;  im[IDX(tid+256)] = c1i + d1i;
        float fr = c1r - d1r, fi = c1i - d1i;
        re[IDX(tid+384)] = fr * wBr - fi * wBi;
        im[IDX(tid+384)] = fr * wBi + fi * wBr;
    }
    __syncthreads();

    fwd_pass<6>(re, im, d_T4r, d_T4i, tid);
    for (int f = tid; f < NFREQ; f += 128) {
        int bd = d_band[f];
        float m0 = (bd >= 0) ? s_m0[bd] : 0.0f;
        float m1 = (bd >= 0) ? s_m1[bd] : 0.0f;
        s_a[f] = 0.5f * (m0 + m1);
        s_d[f] = 0.5f * (m0 - m1);
    }
    __syncthreads();
    fwd_pass<4>(re, im, d_T16r, d_T16i, tid);
    __syncthreads();
    fwd_p2(re, im, tid);
    __syncthreads();

    float zr[4], zi[4];
    {
        float4 vr = reinterpret_cast<float4*>(re)[VIDX(tid)];
        float4 vi = reinterpret_cast<float4*>(im)[VIDX(tid)];
        zr[0] = vr.x + vr.y;  zr[1] = vr.x - vr.y;
        zr[2] = vr.z + vr.w;  zr[3] = vr.z - vr.w;
        zi[0] = vi.x + vi.y;  zi[1] = vi.x - vi.y;
        zi[2] = vi.z + vi.w;  zi[3] = vi.z - vi.w;
        float4 or_, oi_;
        or_.x = zr[0]; or_.y = zr[1]; or_.z = zr[2]; or_.w = zr[3];
        oi_.x = zi[0]; oi_.y = zi[1]; oi_.z = zi[2]; oi_.w = zi[3];
        reinterpret_cast<float4*>(re)[VIDX(tid)] = or_;
        reinterpret_cast<float4*>(im)[VIDX(tid)] = oi_;
    }
    __syncthreads();

    {
        float wr_[4], wi_[4];
        #pragma unroll
        for (int c = 0; c < 4; ++c) {
            int p  = 4 * tid + c;
            int k  = brev9(p);
            int p2 = brev9((NFFT - k) & (NFFT - 1));
            int f  = (k <= 256) ? k : NFFT - k;
            float a  = s_a[f];
            float dd = s_d[f];
            wr_[c] = a * zr[c] + dd * re[IDX(p2)];
            wi_[c] = a * zi[c] - dd * im[IDX(p2)];
        }
        float a1r = wr_[0] + wr_[1], a1i = wi_[0] + wi_[1];
        float b1r = wr_[0] - wr_[1], b1i = wi_[0] - wi_[1];
        float c1r = wr_[2] + wr_[3], c1i = wi_[2] + wi_[3];
        float d1r = wr_[2] - wr_[3], d1i = wi_[2] - wi_[3];
        float4 or_, oi_;
        or_.x = a1r + c1r;  oi_.x = a1i + c1i;
        or_.z = a1r - c1r;  oi_.z = a1i - c1i;
        float vdr = -d1i, vdi = d1r;
        or_.y = b1r + vdr;  oi_.y = b1i + vdi;
        or_.w = b1r - vdr;  oi_.w = b1i - vdi;
        __syncthreads();
        reinterpret_cast<float4*>(re)[VIDX(tid)] = or_;
        reinterpret_cast<float4*>(im)[VIDX(tid)] = oi_;
    }
    __syncthreads();

    inv_pass<2>(re, im, d_T32r, d_T32i, tid);  __syncthreads();
    inv_pass<4>(re, im, d_T8r,  d_T8i,  tid);  __syncthreads();
    inv_pass<6>(re, im, d_T2r,  d_T2i,  tid);  __syncthreads();

    // fused: inverse stage (8) + windowed fp16 global store
    {
        const float scale = 1.0f / (float)NFFT;
        __half* y0 = d_yf + ((size_t)b * TPAD + t0) * NFFT;
        __half* y1 = d_yf + ((size_t)b * TPAD + t1) * NFFT;
        #pragma unroll
        for (int r = 0; r < 2; ++r) {
            int p = tid + r * 128;
            float wr = __ldg(&d_T1r[p]), wi = -__ldg(&d_T1i[p]);
            float ar = re[IDX(p)],     ai = im[IDX(p)];
            float br = re[IDX(p+256)], bi = im[IDX(p+256)];
            float vr = br * wr - bi * wi;
            float vi = br * wi + bi * wr;
            float wlo = __ldg(&d_win[p])     * scale;
            float whi = __ldg(&d_win[p+256]) * scale;
            y0[p]       = __float2half_rn((ar + vr) * wlo);
            y0[p + 256] = __float2half_rn((ar - vr) * whi);
            if (t1v) {
                y1[p]       = __float2half_rn((ai + vi) * wlo);
                y1[p + 256] = __float2half_rn((ai - vi) * whi);
            }
        }
    }
}

// ---------------------------------------------------------------------------
// Quad-vectorized OLA gather: 4 samples per thread (same frame set, since
// 4 | HOP). fp16 frame reads as half2 pairs, float4 denom, float4 store.
// ---------------------------------------------------------------------------
__global__ __launch_bounds__(256) void gather_k(float* __restrict__ out) {
    const int b   = blockIdx.y;
    const int tid = threadIdx.x;
    const int qd  = blockIdx.x * 256 + tid;
    __shared__ float s_red[256];
    float m = 0.0f;

    if (qd < LEN / 4) {
        const int n  = qd * 4;
        const int p  = n + PADS;
        const int tb = p >> 7;
        const int k0 = p & (HOPL - 1);

        float s0 = 0.f, s1 = 0.f, s2 = 0.f, s3 = 0.f;
        float e0 = 0.f, e1 = 0.f, e2 = 0.f, e3 = 0.f;
        #pragma unroll
        for (int jj = 0; jj < 4; ++jj) {
            int t = tb - jj;
            if (t >= 0 && t < TFR) {
                int k = k0 + (jj << 7);
                const __half2* f2 = reinterpret_cast<const __half2*>(
                    d_yf + ((size_t)b * TPAD + t) * NFFT + k);
                __half2 u0 = f2[0], u1 = f2[1];
                float2 a = __half22float2(u0);
                float2 c = __half22float2(u1);
                s0 += a.x; s1 += a.y; s2 += c.x; s3 += c.y;
                float4 w4 = *reinterpret_cast<const float4*>(&d_win2[k]);
                e0 += w4.x; e1 += w4.y; e2 += w4.z; e3 += w4.w;
            }
        }
        e0 = (e0 > 1e-11f) ? e0 : 1.0f;
        e1 = (e1 > 1e-11f) ? e1 : 1.0f;
        e2 = (e2 > 1e-11f) ? e2 : 1.0f;
        e3 = (e3 > 1e-11f) ? e3 : 1.0f;
        float4 y;
        y.x = s0 / e0;  y.y = s1 / e1;  y.z = s2 / e2;  y.w = s3 / e3;
        *reinterpret_cast<float4*>(out + (size_t)b * LEN + n) = y;
        m = fmaxf(fmaxf(fabsf(y.x), fabsf(y.y)), fmaxf(fabsf(y.z), fabsf(y.w)));
    }

    s_red[tid] = m;
    __syncthreads();
    for (int off = 128; off > 0; off >>= 1) {
        if (tid < off) s_red[tid] = fmaxf(s_red[tid], s_red[tid + off]);
        __syncthreads();
    }
    if (tid == 0) atomicMax(&d_maxb[b], __float_as_uint(s_red[0]));
}

// ---------------------------------------------------------------------------
__global__ __launch_bounds__(256) void norm_k(float* __restrict__ out) {
    const int b  = blockIdx.y;
    const int n4 = blockIdx.x * 256 + threadIdx.x;
    if (n4 >= LEN / 4) return;
    float mx  = __uint_as_float(d_maxb[b]);
    float inv = 1.0f / (mx + 1e-8f);
    float4* ptr = reinterpret_cast<float4*>(out + (size_t)b * LEN);
    float4 v = ptr[n4];
    v.x *= inv; v.y *= inv; v.z *= inv; v.w *= inv;
    ptr[n4] = v;
}

// ---------------------------------------------------------------------------
extern "C" void kernel_launch(void* const* d_in, const int* in_sizes, int n_in,
                              void* d_out, int out_size) {
    (void)in_sizes; (void)n_in; (void)out_size;
    const float* mag   = (const float*)d_in[0];   // [32, 80, 2000]
    const float* noise = (const float*)d_in[1];   // [32, 320000]
    float* out = (float*)d_out;                   // [32, 320000]

    init_tables_k<<<1, 512>>>();
    frame_k<<<dim3(NPAIR, BATCH), 128>>>(mag, noise);
    gather_k<<<dim3((LEN / 4 + 255) / 256, BATCH), 256>>>(out);
    norm_k<<<dim3((LEN / 4 + 255) / 256, BATCH), 256>>>(out);
}

// round 6
// speedup vs baseline: 4.6280x; 1.3668x over previous
#include <cuda_runtime.h>
#include <cuda_fp16.h>
#include <math.h>

#ifndef M_PI
#define M_PI 3.14159265358979323846
#endif

#define NB     80
#define NFFT   512
#define HOPL   128
#define PADS   256
#define NFREQ  257
#define NFRM   2000
#define BATCH  32
#define LEN    320000
#define TFR    2501
#define TPAD   2502
#define NPAIR  1251
#define NBLKX  ((NPAIR + 1) / 2)

#define C_SQ 0.70710678118654752440f

// shared padding: 1 float per 8 (conflict-free for stride-8 and contiguous octets)
__device__ __forceinline__ int IDX(int i) { return i + (i >> 3); }
#define SPAD (NFFT + NFFT/8)   // 576

// ---- static device scratch ----
__device__ float d_win[NFFT];
__device__ float d_win2[NFFT];
__device__ int   d_band[NFREQ];
__device__ float d_T1r[64],  d_T1i[64];   // W^t,  t<64
__device__ float d_T8r[8],   d_T8i[8];    // W^{8j}, j<8
__device__ __half d_yf[(size_t)BATCH * TPAD * NFFT];  // ~82 MB frame outputs (fp16)
__device__ unsigned int d_maxb[BATCH];

__device__ __forceinline__ int brev9(int p) {
    return (int)(__brev((unsigned)p) >> 23);
}

// ---------------------------------------------------------------------------
__global__ void init_tables_k() {
    __shared__ float s_edges[NB + 1];
    int j = threadIdx.x;

    if (j <= NB) {
        double mel_max = 2595.0 * log10(1.0 + 8000.0 / 700.0);
        double delta   = mel_max / (double)NB;
        double mel     = (j == NB) ? mel_max : (double)j * delta;
        double hz      = 700.0 * (pow(10.0, mel / 2595.0) - 1.0);
        s_edges[j]     = (float)(hz / 8000.0);
    }
    if (j < NFFT) {
        double w = 0.5 * (1.0 - cos(2.0 * M_PI * (double)j / (double)NFFT));
        d_win[j]  = (float)w;
        d_win2[j] = (float)(w * w);
    }
    if (j < 64) { double a = -2.0*M_PI*(double)j/512.0;     d_T1r[j]=(float)cos(a); d_T1i[j]=(float)sin(a); }
    if (j < 8)  { double a = -2.0*M_PI*(double)(8*j)/512.0; d_T8r[j]=(float)cos(a); d_T8i[j]=(float)sin(a); }
    if (j < BATCH) d_maxb[j] = 0u;
    __syncthreads();
    if (j < NFREQ) {
        float freq = (float)j / 256.0f;
        int idx = 0;
        #pragma unroll 1
        for (int e = 0; e <= NB; ++e) idx += (s_edges[e] <= freq) ? 1 : 0;  // searchsorted 'right'
        int band = idx - 1;
        d_band[j] = (band >= 0 && band < NB) ? band : -1;
    }
}

// ---------------------------------------------------------------------------
__device__ __forceinline__ void bfly_f(float& ar, float& ai, float& br, float& bi,
                                       float wr, float wi) {
    float tr = ar - br, ti = ai - bi;
    ar += br; ai += bi;
    br = tr * wr - ti * wi;
    bi = tr * wi + ti * wr;
}
__device__ __forceinline__ void bfly_i(float& ar, float& ai, float& br, float& bi,
                                       float wr, float wi) {
    float tr = br * wr - bi * wi, ti = br * wi + bi * wr;
    br = ar - tr; bi = ai - ti;
    ar += tr; ai += ti;
}

// 3 forward DIF stages on 8 register points (pair strides 4,2,1), base twiddle w1.
__device__ __forceinline__ void fwd_oct(float* xr, float* xi, float w1r, float w1i) {
    float w2r = w1r*w1r - w1i*w1i, w2i = 2.f*w1r*w1i;
    float w4r = w2r*w2r - w2i*w2i, w4i = 2.f*w2r*w2i;
    float sC = C_SQ*(w1r + w1i), dC = C_SQ*(w1i - w1r);
    // stage A: pairs (r, r+4), tw = w1 * W^{64r}
    bfly_f(xr[0],xi[0], xr[4],xi[4], w1r,  w1i);
    bfly_f(xr[1],xi[1], xr[5],xi[5], sC,   dC);
    bfly_f(xr[2],xi[2], xr[6],xi[6], w1i, -w1r);
    bfly_f(xr[3],xi[3], xr[7],xi[7], dC,  -sC);
    // stage B: pairs (r, r+2), tw = w2 * {1, -i}
    bfly_f(xr[0],xi[0], xr[2],xi[2], w2r,  w2i);
    bfly_f(xr[1],xi[1], xr[3],xi[3], w2i, -w2r);
    bfly_f(xr[4],xi[4], xr[6],xi[6], w2r,  w2i);
    bfly_f(xr[5],xi[5], xr[7],xi[7], w2i, -w2r);
    // stage C: pairs (r, r+1), tw = w4
    bfly_f(xr[0],xi[0], xr[1],xi[1], w4r, w4i);
    bfly_f(xr[2],xi[2], xr[3],xi[3], w4r, w4i);
    bfly_f(xr[4],xi[4], xr[5],xi[5], w4r, w4i);
    bfly_f(xr[6],xi[6], xr[7],xi[7], w4r, w4i);
}

// 3 inverse DIT stages on 8 register points (pair strides 1,2,4), base twiddle w1 (conj inside).
__device__ __forceinline__ void inv_oct(float* xr, float* xi, float w1r, float w1i) {
    float w2r = w1r*w1r - w1i*w1i, w2i = 2.f*w1r*w1i;
    float w4r = w2r*w2r - w2i*w2i, w4i = 2.f*w2r*w2i;
    // stage A: pairs (r, r+1), tw = conj(w4)
    bfly_i(xr[0],xi[0], xr[1],xi[1], w4r, -w4i);
    bfly_i(xr[2],xi[2], xr[3],xi[3], w4r, -w4i);
    bfly_i(xr[4],xi[4], xr[5],xi[5], w4r, -w4i);
    bfly_i(xr[6],xi[6], xr[7],xi[7], w4r, -w4i);
    // stage B: pairs (r, r+2), tw = conj(w2) * {1, i}
    bfly_i(xr[0],xi[0], xr[2],xi[2], w2r, -w2i);
    bfly_i(xr[1],xi[1], xr[3],xi[3], w2i,  w2r);
    bfly_i(xr[4],xi[4], xr[6],xi[6], w2r, -w2i);
    bfly_i(xr[5],xi[5], xr[7],xi[7], w2i,  w2r);
    // stage C: pairs (r, r+4), tw = conj(w1) * conj(W^{64r})
    float sC = C_SQ*(w1r + w1i), dC = C_SQ*(w1r - w1i);
    bfly_i(xr[0],xi[0], xr[4],xi[4], w1r, -w1i);
    bfly_i(xr[1],xi[1], xr[5],xi[5], sC,   dC);
    bfly_i(xr[2],xi[2], xr[6],xi[6], w1i,  w1r);
    bfly_i(xr[3],xi[3], xr[7],xi[7], -dC,  sC);
}

// ---------------------------------------------------------------------------
// 128 threads = 2 FFT units of 64 threads; each unit: one frame-pair.
// 8 points/thread; 3 fused passes per direction; 5 shared exchanges total.
// ---------------------------------------------------------------------------
__global__ __launch_bounds__(128) void frame_k(const float* __restrict__ mag,
                                               const float* __restrict__ noise) {
    const int u  = threadIdx.x >> 6;
    const int t  = threadIdx.x & 63;
    const int b  = blockIdx.y;
    int q = blockIdx.x * 2 + u;
    const bool qv = (q < NPAIR);
    if (!qv) q = NPAIR - 1;
    const int t0 = 2 * q;
    const int t1 = 2 * q + 1;
    const bool t1v = qv && (t1 < TFR);
    const int t1c = (t1 < TFR) ? t1 : (TFR - 1);

    __shared__ __align__(16) float sre[2][SPAD];
    __shared__ __align__(16) float sim[2][SPAD];
    __shared__ float s_a[2][NFREQ], s_d[2][NFREQ];
    __shared__ float s_m0[2][NB],  s_m1[2][NB];

    float* Re = sre[u];
    float* Im = sim[u];

    const int lo3 = t & 7, hi3 = t >> 3;

    // phase 0: band magnitudes + global load + forward pass 1 (stages 8,7,6)
    for (int n = t; n < NB; n += 64) {
        const float* mrow = mag + ((size_t)b * NB + n) * NFRM;
        {
            double pos = (double)t0 * (1999.0 / 2500.0);
            int   i0  = (int)pos;
            float wfr = (float)(pos - (double)i0);
            int   i1  = min(i0 + 1, NFRM - 1);
            s_m0[u][n] = mrow[i0] * (1.0f - wfr) + mrow[i1] * wfr;
        }
        {
            double pos = (double)t1c * (1999.0 / 2500.0);
            int   i0  = (int)pos;
            float wfr = (float)(pos - (double)i0);
            int   i1  = min(i0 + 1, NFRM - 1);
            s_m1[u][n] = mrow[i0] * (1.0f - wfr) + mrow[i1] * wfr;
        }
    }

    float xr[8], xi[8];
    {
        const float* nb_ = noise + (size_t)b * LEN;
        const int base = t0 * HOPL - PADS;
        #pragma unroll
        for (int r = 0; r < 8; ++r) {
            int p = t + 64 * r;
            int m0i = base + p;
            if (m0i < 0)         m0i = -m0i;
            else if (m0i >= LEN) m0i = 2 * LEN - 2 - m0i;
            int m1i = base + HOPL + p;
            if (m1i < 0)         m1i = -m1i;
            else if (m1i >= LEN) m1i = 2 * LEN - 2 - m1i;
            float w = __ldg(&d_win[p]);
            xr[r] = nb_[m0i] * w;
            xi[r] = nb_[m1i] * w;
        }
        fwd_oct(xr, xi, __ldg(&d_T1r[t]), __ldg(&d_T1i[t]));
        #pragma unroll
        for (int r = 0; r < 8; ++r) {
            Re[IDX(t + 64*r)] = xr[r];
            Im[IDX(t + 64*r)] = xi[r];
        }
    }
    __syncthreads();

    // forward pass 2 (stages 5,4,3) on point set {lo3 + 8r + 64*hi3}; in place.
    {
        #pragma unroll
        for (int r = 0; r < 8; ++r) {
            int p = lo3 + 8*r + 64*hi3;
            xr[r] = Re[IDX(p)];  xi[r] = Im[IDX(p)];
        }
        fwd_oct(xr, xi, __ldg(&d_T8r[lo3]), __ldg(&d_T8i[lo3]));
        #pragma unroll
        for (int r = 0; r < 8; ++r) {
            int p = lo3 + 8*r + 64*hi3;
            Re[IDX(p)] = xr[r];  Im[IDX(p)] = xi[r];
        }
    }
    // mask coefficients (reads s_m written before last sync)
    for (int f = t; f < NFREQ; f += 64) {
        int bd = d_band[f];
        float m0 = (bd >= 0) ? s_m0[u][bd] : 0.0f;
        float m1 = (bd >= 0) ? s_m1[u][bd] : 0.0f;
        s_a[u][f] = 0.5f * (m0 + m1);
        s_d[u][f] = 0.5f * (m0 - m1);
    }
    __syncthreads();

    // forward pass 3 (stages 2,1,0) on contiguous {8t..8t+7}; publish Z.
    {
        #pragma unroll
        for (int r = 0; r < 8; ++r) {
            xr[r] = Re[IDX(8*t + r)];  xi[r] = Im[IDX(8*t + r)];
        }
        fwd_oct(xr, xi, 1.0f, 0.0f);
        #pragma unroll
        for (int r = 0; r < 8; ++r) {
            Re[IDX(8*t + r)] = xr[r];  Im[IDX(8*t + r)] = xi[r];
        }
    }
    __syncthreads();

    // two-frame mask W[k] = a*Z[k] + d*conj(Z[N-k]) + inverse stages 0,1,2
    float wr_[8], wi_[8];
    {
        #pragma unroll
        for (int r = 0; r < 8; ++r) {
            int p  = 8*t + r;
            int k  = brev9(p);
            int p2 = brev9((NFFT - k) & (NFFT - 1));
            int f  = (k <= 256) ? k : NFFT - k;
            float a  = s_a[u][f];
            float dd = s_d[u][f];
            wr_[r] = a * xr[r] + dd * Re[IDX(p2)];
            wi_[r] = a * xi[r] - dd * Im[IDX(p2)];
        }
        inv_oct(wr_, wi_, 1.0f, 0.0f);
    }
    __syncthreads();   // all partner reads done before overwrite
    {
        #pragma unroll
        for (int r = 0; r < 8; ++r) {
            Re[IDX(8*t + r)] = wr_[r];  Im[IDX(8*t + r)] = wi_[r];
        }
    }
    __syncthreads();

    // inverse pass 2 (stages 3,4,5) on {lo3 + 8r + 64*hi3}; in place.
    {
        #pragma unroll
        for (int r = 0; r < 8; ++r) {
            int p = lo3 + 8*r + 64*hi3;
            xr[r] = Re[IDX(p)];  xi[r] = Im[IDX(p)];
        }
        inv_oct(xr, xi, __ldg(&d_T8r[lo3]), __ldg(&d_T8i[lo3]));
        #pragma unroll
        for (int r = 0; r < 8; ++r) {
            int p = lo3 + 8*r + 64*hi3;
            Re[IDX(p)] = xr[r];  Im[IDX(p)] = xi[r];
        }
    }
    __syncthreads();

    // inverse pass 3 (stages 6,7,8) on {t + 64r} + windowed fp16 store.
    {
        #pragma unroll
        for (int r = 0; r < 8; ++r) {
            int p = t + 64*r;
            xr[r] = Re[IDX(p)];  xi[r] = Im[IDX(p)];
        }
        inv_oct(xr, xi, __ldg(&d_T1r[t]), __ldg(&d_T1i[t]));

        const float scale = 1.0f / (float)NFFT;
        __half* y0 = d_yf + ((size_t)b * TPAD + t0) * NFFT;
        __half* y1 = d_yf + ((size_t)b * TPAD + t1) * NFFT;
        #pragma unroll
        for (int r = 0; r < 8; ++r) {
            int p = t + 64*r;
            float w = __ldg(&d_win[p]) * scale;
            if (qv)  y0[p] = __float2half_rn(xr[r] * w);
            if (t1v) y1[p] = __float2half_rn(xi[r] * w);
        }
    }
}

// ---------------------------------------------------------------------------
// Quad-vectorized OLA gather: 4 samples per thread, fused max reduction.
// ---------------------------------------------------------------------------
__global__ __launch_bounds__(256) void gather_k(float* __restrict__ out) {
    const int b   = blockIdx.y;
    const int tid = threadIdx.x;
    const int qd  = blockIdx.x * 256 + tid;
    __shared__ float s_red[256];
    float m = 0.0f;

    if (qd < LEN / 4) {
        const int n  = qd * 4;
        const int p  = n + PADS;
        const int tb = p >> 7;
        const int k0 = p & (HOPL - 1);

        float s0 = 0.f, s1 = 0.f, s2 = 0.f, s3 = 0.f;
        float e0 = 0.f, e1 = 0.f, e2 = 0.f, e3 = 0.f;
        #pragma unroll
        for (int jj = 0; jj < 4; ++jj) {
            int t = tb - jj;
            if (t >= 0 && t < TFR) {
                int k = k0 + (jj << 7);
                const __half2* f2 = reinterpret_cast<const __half2*>(
                    d_yf + ((size_t)b * TPAD + t) * NFFT + k);
                __half2 u0 = f2[0], u1 = f2[1];
                float2 a = __half22float2(u0);
                float2 c = __half22float2(u1);
                s0 += a.x; s1 += a.y; s2 += c.x; s3 += c.y;
                float4 w4 = *reinterpret_cast<const float4*>(&d_win2[k]);
                e0 += w4.x; e1 += w4.y; e2 += w4.z; e3 += w4.w;
            }
        }
        e0 = (e0 > 1e-11f) ? e0 : 1.0f;
        e1 = (e1 > 1e-11f) ? e1 : 1.0f;
        e2 = (e2 > 1e-11f) ? e2 : 1.0f;
        e3 = (e3 > 1e-11f) ? e3 : 1.0f;
        float4 y;
        y.x = s0 / e0;  y.y = s1 / e1;  y.z = s2 / e2;  y.w = s3 / e3;
        *reinterpret_cast<float4*>(out + (size_t)b * LEN + n) = y;
        m = fmaxf(fmaxf(fabsf(y.x), fabsf(y.y)), fmaxf(fabsf(y.z), fabsf(y.w)));
    }

    s_red[tid] = m;
    __syncthreads();
    for (int off = 128; off > 0; off >>= 1) {
        if (tid < off) s_red[tid] = fmaxf(s_red[tid], s_red[tid + off]);
        __syncthreads();
    }
    if (tid == 0) atomicMax(&d_maxb[b], __float_as_uint(s_red[0]));
}

// ---------------------------------------------------------------------------
__global__ __launch_bounds__(256) void norm_k(float* __restrict__ out) {
    const int b  = blockIdx.y;
    const int n4 = blockIdx.x * 256 + threadIdx.x;
    if (n4 >= LEN / 4) return;
    float mx  = __uint_as_float(d_maxb[b]);
    float inv = 1.0f / (mx + 1e-8f);
    float4* ptr = reinterpret_cast<float4*>(out + (size_t)b * LEN);
    float4 v = ptr[n4];
    v.x *= inv; v.y *= inv; v.z *= inv; v.w *= inv;
    ptr[n4] = v;
}

// ---------------------------------------------------------------------------
extern "C" void kernel_launch(void* const* d_in, const int* in_sizes, int n_in,
                              void* d_out, int out_size) {
    (void)in_sizes; (void)n_in; (void)out_size;
    const float* mag   = (const float*)d_in[0];   // [32, 80, 2000]
    const float* noise = (const float*)d_in[1];   // [32, 320000]
    float* out = (float*)d_out;                   // [32, 320000]

    init_tables_k<<<1, 512>>>();
    frame_k<<<dim3(NBLKX, BATCH), 128>>>(mag, noise);
    gather_k<<<dim3((LEN / 4 + 255) / 256, BATCH), 256>>>(out);
    norm_k<<<dim3((LEN / 4 + 255) / 256, BATCH), 256>>>(out);
}